// round 6
// baseline (speedup 1.0000x reference)
#include <cuda_runtime.h>
#include <cuda_bf16.h>
#include <math.h>

#define BB   8
#define QQ   2048
#define KK2  2048
#define FF   512
#define FVV  512
#define NTHREADS 256

// ---------------- scratch (device globals; no runtime allocation) ----------------
// bf16 A-blob (64x64): [ks4][mf4][lane32][4 b32] ; regs: r0=(g,2t..),r1=(g+8,2t..),r2=(g,2t+8..),r3=(g+8,2t+8..)
// bf16 B-blob (64x64): [ks4][nf8][lane32][2 b32] ; r0=(k=2t..,n=g), r1=(k=2t+8..,n=g)
// tf32 B-blob (64x64): [ks8][nf8][lane32][2 b32] ; r0=(k=t,n=g), r1=(k=t+4,n=g)
__device__ __align__(16) unsigned g_Qpb[4194304];     // (b, qt32, ft8) bf16 A-blobs  16.8MB
__device__ __align__(16) unsigned g_Kpb[4194304];     // (b, kt32, ft8) bf16 B-blobs  16.8MB
__device__ __align__(16) float    g_Vp [8388608];     // (b, fvt8, kt32) tf32 B-blobs 33.5MB
__device__ __align__(16) __nv_bfloat16 g_E[33554432]; // exp(logits) row-major        67MB
__device__ float g_linv[BB*QQ];
__device__ int   g_mask_is_int32;

// ---------------- helpers ----------------
__device__ __forceinline__ unsigned to_tf32(float f){
    unsigned u; asm("cvt.rna.tf32.f32 %0, %1;" : "=r"(u) : "f"(f)); return u;
}
__device__ __forceinline__ void mma_tf32(float c[4], const unsigned* a, const unsigned* b){
    asm volatile("mma.sync.aligned.m16n8k8.row.col.f32.tf32.tf32.f32 "
        "{%0,%1,%2,%3}, {%4,%5,%6,%7}, {%8,%9}, {%0,%1,%2,%3};"
        : "+f"(c[0]), "+f"(c[1]), "+f"(c[2]), "+f"(c[3])
        : "r"(a[0]), "r"(a[1]), "r"(a[2]), "r"(a[3]), "r"(b[0]), "r"(b[1]));
}
__device__ __forceinline__ void mma_bf16(float c[4], const unsigned* a, const unsigned* b){
    asm volatile("mma.sync.aligned.m16n8k16.row.col.f32.bf16.bf16.f32 "
        "{%0,%1,%2,%3}, {%4,%5,%6,%7}, {%8,%9}, {%0,%1,%2,%3};"
        : "+f"(c[0]), "+f"(c[1]), "+f"(c[2]), "+f"(c[3])
        : "r"(a[0]), "r"(a[1]), "r"(a[2]), "r"(a[3]), "r"(b[0]), "r"(b[1]));
}
// exp on the FMA pipe: 2^(x*log2e), deg-5 poly (rel err ~2e-7 for |x| < 15)
__device__ __forceinline__ float fexp(float x){
    float t = x * 1.4426950408889634f;
    float r = rintf(t);
    float f = t - r;
    float p = 1.3333558146428443e-3f;
    p = fmaf(p, f, 9.618129107628477e-3f);
    p = fmaf(p, f, 5.550410866482158e-2f);
    p = fmaf(p, f, 2.402265069591007e-1f);
    p = fmaf(p, f, 6.931471805599453e-1f);
    p = fmaf(p, f, 1.0f);
    return __int_as_float(((int)r + 127) << 23) * p;
}
// rsqrt on FMA pipe, 2 Newton steps (~1e-6 rel)
__device__ __forceinline__ float frsqrt2(float x){
    float y = __int_as_float(0x5f3759df - (__float_as_int(x) >> 1));
    y = y * (1.5f - 0.5f * x * y * y);
    y = y * (1.5f - 0.5f * x * y * y);
    return y;
}

// ---------------- mask dtype probe ----------------
__global__ void detect_mask_kernel(const unsigned char* am){
    unsigned nz = 0;
    #pragma unroll 8
    for (int i = 0; i < 1024; i++) nz |= am[4*i+1] | am[4*i+2] | am[4*i+3];
    g_mask_is_int32 = (nz == 0u) ? 1 : 0;
}

// ---------------- prep Q -> bf16 A-fragment blobs ----------------
__global__ void __launch_bounds__(NTHREADS) prep_qb_kernel(const float* __restrict__ q){
    int w = blockIdx.x * 8 + (threadIdx.x >> 5);
    int lane = threadIdx.x & 31, g = lane >> 2, t = lane & 3;
    int mf = w & 3, ks = (w>>2)&3, ft = (w>>4)&7, qt = (w>>7)&31, b = w>>12;
    unsigned rr[4];
    #pragma unroll
    for (int rh = 0; rh < 2; rh++){
        int row = qt*64 + mf*16 + g + 8*rh;
        const float* qp = q + ((size_t)(b*QQ + row))*FF + ft*64 + ks*16 + 2*t;
        float2 x0 = *(const float2*)qp;
        float2 x1 = *(const float2*)(qp + 8);
        __nv_bfloat162 h0 = __floats2bfloat162_rn(x0.x, x0.y);
        __nv_bfloat162 h1 = __floats2bfloat162_rn(x1.x, x1.y);
        rr[rh]   = *(unsigned*)&h0;
        rr[rh+2] = *(unsigned*)&h1;
    }
    size_t blob = ((size_t)((b*32 + qt)*8 + ft))*2048;
    *(uint4*)(g_Qpb + blob + ((ks*4 + mf)*32 + lane)*4) = make_uint4(rr[0],rr[1],rr[2],rr[3]);
}

// ---------------- prep K -> bf16 B-fragment blobs ----------------
__global__ void __launch_bounds__(NTHREADS) prep_kb_kernel(const float* __restrict__ k){
    int w = blockIdx.x * 8 + (threadIdx.x >> 5);
    int lane = threadIdx.x & 31, g = lane >> 2, t = lane & 3;
    int nf = w & 7, ks = (w>>3)&3, ft = (w>>5)&7, kt = (w>>8)&31, b = w>>13;
    int n = kt*64 + nf*8 + g;
    const float* kp = k + ((size_t)(b*KK2 + n))*FF + ft*64 + ks*16 + 2*t;
    float2 x0 = *(const float2*)kp;
    float2 x1 = *(const float2*)(kp + 8);
    __nv_bfloat162 h0 = __floats2bfloat162_rn(x0.x, x0.y);
    __nv_bfloat162 h1 = __floats2bfloat162_rn(x1.x, x1.y);
    size_t blob = ((size_t)((b*32 + kt)*8 + ft))*2048;
    *(uint2*)(g_Kpb + blob + ((ks*8 + nf)*32 + lane)*2) =
        make_uint2(*(unsigned*)&h0, *(unsigned*)&h1);
}

// ---------------- prep V -> tf32 B-fragment blobs (contraction = seq-k, n = fv) ----------------
__global__ void __launch_bounds__(NTHREADS) prep_v_kernel(const float* __restrict__ v){
    int w = blockIdx.x * 8 + (threadIdx.x >> 5);
    int lane = threadIdx.x & 31, g = lane >> 2, t = lane & 3;
    int nf = w & 7, ks = (w>>3)&7, kt = (w>>6)&31, fvt = (w>>11)&7, b = w>>14;
    unsigned rr[2];
    #pragma unroll
    for (int j = 0; j < 2; j++){
        int kk = kt*64 + ks*8 + t + 4*j;
        int fv = fvt*64 + nf*8 + g;
        rr[j] = to_tf32(v[((size_t)(b*KK2 + kk))*FVV + fv]);
    }
    size_t blob = ((size_t)((b*8 + fvt)*32 + kt))*4096;
    *(uint2*)(g_Vp + blob + ((ks*8 + nf)*32 + lane)*2) = make_uint2(rr[0], rr[1]);
}

// ---------------- pass1: S = QK^T * scale (bf16 mma); E = exp(S); linv = 1/rowsum ----------------
__global__ void __launch_bounds__(NTHREADS, 1) pass1_kernel(void){
    extern __shared__ unsigned smem_u[];
    unsigned* smQ = smem_u;                    // 16384 words = 64KB
    float* l_s = (float*)(smem_u + 16384);     // 8 warps * 64 rows

    int tid = threadIdx.x, lane = tid & 31, wc = tid >> 5;
    int g = lane >> 2, t = lane & 3;
    int b = blockIdx.x >> 5, qt = blockIdx.x & 31;
    const float SCALE = 0.044194173824159216f;  // 1/sqrt(512)

    {   // stage all 8 Q blobs for this q-tile
        const uint4* src = (const uint4*)(g_Qpb + ((size_t)((b*32 + qt)*8))*2048);
        uint4* dst = (uint4*)smQ;
        #pragma unroll
        for (int i = 0; i < 16; i++) dst[tid + 256*i] = src[tid + 256*i];
    }
    __syncthreads();

    float rsl[4][2];
    #pragma unroll
    for (int a=0;a<4;a++){ rsl[a][0]=0.f; rsl[a][1]=0.f; }

    #pragma unroll 1
    for (int kb = 0; kb < 8; kb++){
        int kt = kb*4 + (wc >> 1);
        int nb = (wc & 1) * 4;

        float C[4][4][4];
        #pragma unroll
        for (int a=0;a<4;a++)
            #pragma unroll
            for (int bb=0;bb<4;bb++)
                #pragma unroll
                for (int c=0;c<4;c++) C[a][bb][c]=0.f;

        #pragma unroll 1
        for (int ft = 0; ft < 8; ft++){
            const unsigned* As = smQ + ft*2048;
            const unsigned* Bb = g_Kpb + ((size_t)((b*32 + kt)*8 + ft))*2048;
            #pragma unroll
            for (int ks = 0; ks < 4; ks++){
                uint4 Af[4];
                #pragma unroll
                for (int mf=0; mf<4; mf++)
                    Af[mf] = *(const uint4*)(As + ((ks*4 + mf)*32 + lane)*4);
                uint2 Bf[4];
                #pragma unroll
                for (int nf=0; nf<4; nf++)
                    Bf[nf] = *(const uint2*)(Bb + ((ks*8 + nb + nf)*32 + lane)*2);
                #pragma unroll
                for (int mf=0; mf<4; mf++)
                    #pragma unroll
                    for (int nf=0; nf<4; nf++)
                        mma_bf16(C[mf][nf], (const unsigned*)&Af[mf], (const unsigned*)&Bf[nf]);
            }
        }

        // exp + E store + row-sum partials
        #pragma unroll
        for (int mf = 0; mf < 4; mf++)
            #pragma unroll
            for (int rh = 0; rh < 2; rh++){
                int row = qt*64 + mf*16 + g + 8*rh;
                float rs = 0.f;
                #pragma unroll
                for (int nf = 0; nf < 4; nf++){
                    float e0 = fexp(C[mf][nf][rh*2+0] * SCALE);
                    float e1 = fexp(C[mf][nf][rh*2+1] * SCALE);
                    rs += e0 + e1;
                    int kcol = kb*256 + wc*32 + nf*8 + 2*t;
                    size_t idx = ((size_t)(b*QQ + row))*KK2 + kcol;
                    ((__nv_bfloat162*)g_E)[idx >> 1] = __floats2bfloat162_rn(e0, e1);
                }
                rsl[mf][rh] += rs;
            }
    }

    #pragma unroll
    for (int mf = 0; mf < 4; mf++)
        #pragma unroll
        for (int rh = 0; rh < 2; rh++){
            float rs = rsl[mf][rh];
            rs += __shfl_xor_sync(0xffffffffu, rs, 1);
            rs += __shfl_xor_sync(0xffffffffu, rs, 2);
            if (t == 0) l_s[wc*64 + mf*16 + g + 8*rh] = rs;
        }
    __syncthreads();
    if (tid < 64){
        float s = 0.f;
        #pragma unroll
        for (int w = 0; w < 8; w++) s += l_s[w*64 + tid];
        g_linv[b*QQ + qt*64 + tid] = 1.0f / s;
    }
}

// ---------------- pass2 (fused): W built on the fly in smem; O = W*V (tf32 mma) ----------------
// W smem layout: row-major 64 x 68 (pad) floats per buffer, double-buffered.
// A-frag gather via 4x LDS.32 -> bank = (g*4+t) mod 32, conflict-free.
#define WPAD 68
__global__ void __launch_bounds__(NTHREADS, 1) pass2_kernel(
    float* __restrict__ out,
    const float* __restrict__ cq, const float* __restrict__ ck,
    const unsigned char* __restrict__ am, const unsigned char* __restrict__ al,
    const float* __restrict__ bias)
{
    extern __shared__ float smem[];   // 2 * 64*68 floats = 34816 B
    int tid = threadIdx.x, lane = tid & 31, wc = tid >> 5;
    int g = lane >> 2, t = lane & 3;
    int b = blockIdx.x >> 5, qt = blockIdx.x & 31;

    // build role: thread owns row brow (within q-tile), 16 cols starting at bc0 (within k-tile)
    const int brow = wc*8 + (lane >> 2);
    const int bc0  = (lane & 3) * 16;
    const float2 cqv = *(const float2*)(cq + ((size_t)(b*QQ + qt*64 + brow))*2);
    const float li   = g_linv[b*QQ + qt*64 + brow];
    const size_t erow = ((size_t)(b*QQ + qt*64 + brow))*KK2;
    const float bsc = __ldg(bias);
    const int m32 = g_mask_is_int32;

    float C[4][8][4];
    #pragma unroll
    for (int a=0;a<4;a++)
        #pragma unroll
        for (int n=0;n<8;n++)
            #pragma unroll
            for (int c=0;c<4;c++) C[a][n][c]=0.f;

    #pragma unroll 1
    for (int kt = 0; kt < 32; kt++){
        float* Wb = smem + (kt & 1) * (64*WPAD);

        // ---- build W tile: 2 half-batches of 8 cols to bound register pressure ----
        #pragma unroll
        for (int h = 0; h < 2; h++){
            int cb = kt*64 + bc0 + 8*h;            // global k col of first of 8
            // E: 8 bf16 = 1 uint4
            uint4 eu = *(const uint4*)(g_E + erow + cb);
            const unsigned* ew = (const unsigned*)&eu;
            // masks
            int amv[8], alv[8];
            if (m32){
                const int4* ap = (const int4*)((const int*)am + erow + cb);
                const int4* lp = (const int4*)((const int*)al + erow + cb);
                int4 a0 = ap[0], a1 = ap[1], l0 = lp[0], l1 = lp[1];
                amv[0]=a0.x; amv[1]=a0.y; amv[2]=a0.z; amv[3]=a0.w;
                amv[4]=a1.x; amv[5]=a1.y; amv[6]=a1.z; amv[7]=a1.w;
                alv[0]=l0.x; alv[1]=l0.y; alv[2]=l0.z; alv[3]=l0.w;
                alv[4]=l1.x; alv[5]=l1.y; alv[6]=l1.z; alv[7]=l1.w;
            } else {
                uint2 au = *(const uint2*)(am + erow + cb);
                uint2 lu = *(const uint2*)(al + erow + cb);
                const unsigned char* ab = (const unsigned char*)&au;
                const unsigned char* lb = (const unsigned char*)&lu;
                #pragma unroll
                for (int c = 0; c < 8; c++){ amv[c] = ab[c]; alv[c] = lb[c]; }
            }
            // coords for 8 cols: 16 floats = 4 float4 (L1-broadcast across sharing threads)
            float4 ck4[4];
            #pragma unroll
            for (int i = 0; i < 4; i++)
                ck4[i] = __ldg((const float4*)(ck + ((size_t)(b*KK2 + cb))*2) + i);
            const float2* ckp = (const float2*)&ck4[0];

            float wv[8];
            #pragma unroll
            for (int c = 0; c < 8; c++){
                __nv_bfloat162 e2 = *(__nv_bfloat162*)&ew[c>>1];
                float e = __bfloat162float((c & 1) ? e2.y : e2.x) * li;
                float dx = cqv.x - ckp[c].x;
                float dy = cqv.y - ckp[c].y;
                float r2 = fmaxf(dx*dx + dy*dy, 1e-30f);
                float d  = alv[c] ? 0.f : (r2 * frsqrt2(r2) * bsc);
                float w  = amv[c] ? 0.f : (e - d);
                wv[c] = __uint_as_float(to_tf32(w));
            }
            float* wd = Wb + brow*WPAD + bc0 + 8*h;
            *(float4*)(wd)     = make_float4(wv[0], wv[1], wv[2], wv[3]);
            *(float4*)(wd + 4) = make_float4(wv[4], wv[5], wv[6], wv[7]);
        }
        __syncthreads();

        // ---- mma: A frags from Wb (4x LDS.32, conflict-free), B from g_Vp ----
        const float* Bb = g_Vp + ((size_t)((b*8 + wc)*32 + kt))*4096;
        #pragma unroll
        for (int ks = 0; ks < 8; ks++){
            unsigned Af[4][4];
            #pragma unroll
            for (int mf = 0; mf < 4; mf++){
                #pragma unroll
                for (int r = 0; r < 4; r++){
                    int row = mf*16 + g + 8*(r & 1);
                    int col = ks*8 + t + 4*(r >> 1);
                    Af[mf][r] = __float_as_uint(Wb[row*WPAD + col]);
                }
            }
            uint2 Bf[8];
            #pragma unroll
            for (int nf = 0; nf < 8; nf++)
                Bf[nf] = *(const uint2*)(Bb + ((ks*8 + nf)*32 + lane)*2);
            #pragma unroll
            for (int mf = 0; mf < 4; mf++)
                #pragma unroll
                for (int nf = 0; nf < 8; nf++)
                    mma_tf32(C[mf][nf], Af[mf], (const unsigned*)&Bf[nf]);
        }
        // no second sync needed: next build writes the other buffer; the kt+1 sync
        // transitively orders mma(kt) before build(kt+2).
    }

    // ---- epilogue ----
    #pragma unroll
    for (int mf = 0; mf < 4; mf++)
        #pragma unroll
        for (int rh = 0; rh < 2; rh++){
            int row = qt*64 + mf*16 + g + 8*rh;
            float* orow = out + ((size_t)(b*QQ + row))*FVV;
            #pragma unroll
            for (int nf = 0; nf < 8; nf++){
                int fv = wc*64 + nf*8 + 2*t;
                *(float2*)(orow + fv) = make_float2(C[mf][nf][rh*2+0], C[mf][nf][rh*2+1]);
            }
        }
}

extern "C" void kernel_launch(void* const* d_in, const int* in_sizes, int n_in,
                              void* d_out, int out_size)
{
    const float*         q    = (const float*)d_in[0];
    const float*         k    = (const float*)d_in[1];
    const float*         v    = (const float*)d_in[2];
    const float*         cq   = (const float*)d_in[3];
    const float*         ck   = (const float*)d_in[4];
    const unsigned char* am   = (const unsigned char*)d_in[5];
    const unsigned char* al   = (const unsigned char*)d_in[6];
    const float*         bias = (const float*)d_in[7];
    float*               out  = (float*)d_out;

    static int smem_set = 0;
    if (!smem_set){
        cudaFuncSetAttribute(pass1_kernel, cudaFuncAttributeMaxDynamicSharedMemorySize, 68096);
        cudaFuncSetAttribute(pass2_kernel, cudaFuncAttributeMaxDynamicSharedMemorySize, 34816);
        smem_set = 1;
    }

    detect_mask_kernel<<<1, 1>>>(am);
    prep_qb_kernel<<<4096,  NTHREADS>>>(q);
    prep_kb_kernel<<<8192,  NTHREADS>>>(k);
    prep_v_kernel <<<16384, NTHREADS>>>(v);
    pass1_kernel<<<256, NTHREADS, 68096>>>();
    pass2_kernel<<<256, NTHREADS, 34816>>>(out, cq, ck, am, al, bias);
}